// round 17
// baseline (speedup 1.0000x reference)
#include <cuda_runtime.h>
#include <cuda_fp16.h>
#include <mma.h>

using namespace nvcuda;

#define N_NODES 100000
#define N_EDGES 1600000
#define C 128
#define NG 128
#define LSLOPE 0.01f
#define FULL 0xffffffffu

#define LDA 144            // smem leading dim (halves)
#define GEMM_SMEM ((64 + 128) * LDA * 2)   // 55296 bytes
#define GEMM_GRID ((N_NODES + 63) / 64)    // 1563
#define GEMM_THREADS (GEMM_GRID * 256)     // 400128

// ---------------- scratch (device globals: no allocation allowed) ----------
__device__ __align__(16) __half g_B1h[(size_t)N_NODES * C];  // H fp16 (gathered)
__device__ __align__(16) __half g_B2h[(size_t)N_NODES * C];  // activated layer output fp16
__device__ int   g_deg_i[N_NODES];
__device__ float g_dinv[N_NODES];
__device__ int   g_off[N_NODES + 1];       // CSR offsets (by dst)
__device__ int   g_cursor[N_NODES];        // fill cursors
__device__ __align__(16) int2 g_edge[N_EDGES];  // {src, norm-as-int} per CSR slot
__device__ __align__(16) float g_sums[NG * C];
__device__ float g_cnts[NG];

__device__ __forceinline__ float lrelu(float v) { return v > 0.f ? v : LSLOPE * v; }

// ---------------- WMMA fp16 GEMM: H = X@W -> B1h (fp16) ----------------------
// TRANSFORM=false: X = external fp32 x (layer 1) + FUSED deg histogram/counts.
// TRANSFORM=true : X = g_B2h fp16 (already activated) — pure copy staging.
template <bool TRANSFORM>
__global__ __launch_bounds__(256)
void gemm_kernel(const float* __restrict__ Xext, const float* __restrict__ W,
                 const int* __restrict__ ei, const int* __restrict__ batch)
{
    extern __shared__ char smem[];
    half* Xs = (half*)smem;                    // [64][LDA]
    half* Ws = (half*)(smem + 64 * LDA * 2);   // [128][LDA]

    int tid  = threadIdx.x;
    int row0 = blockIdx.x * 64;

    if (!TRANSFORM) {
#pragma unroll
        for (int it = 0; it < 8; it++) {
            int idx = tid + it * 256;
            int r   = idx >> 5;
            int c4  = (idx & 31) * 4;
            int grow = min(row0 + r, N_NODES - 1);
            float4 v = *(const float4*)(Xext + (size_t)grow * C + c4);
            half2* p = (half2*)(Xs + r * LDA + c4);
            p[0] = __floats2half2_rn(v.x, v.y);
            p[1] = __floats2half2_rn(v.z, v.w);
        }
    } else {
#pragma unroll
        for (int it = 0; it < 4; it++) {
            int idx = tid + it * 256;
            int r   = idx >> 4;
            int c8  = (idx & 15) * 8;
            int grow = min(row0 + r, N_NODES - 1);
            uint4 v = *(const uint4*)(g_B2h + (size_t)grow * C + c8);
            *(uint4*)(Xs + r * LDA + c8) = v;
        }
    }
#pragma unroll
    for (int it = 0; it < 16; it++) {
        int idx = tid + it * 256;
        int r   = idx >> 5;
        int c4  = (idx & 31) * 4;
        float4 v = *(const float4*)(W + (size_t)r * C + c4);
        half2* p = (half2*)(Ws + r * LDA + c4);
        p[0] = __floats2half2_rn(v.x, v.y);
        p[1] = __floats2half2_rn(v.z, v.w);
    }
    __syncthreads();

    int wid   = tid >> 5;
    int warpM = wid & 1;
    int warpN = wid >> 1;

    wmma::fragment<wmma::accumulator, 16, 16, 16, float> c[2][2];
#pragma unroll
    for (int i = 0; i < 2; i++)
#pragma unroll
        for (int j = 0; j < 2; j++) wmma::fill_fragment(c[i][j], 0.0f);

#pragma unroll
    for (int k = 0; k < C; k += 16) {
        wmma::fragment<wmma::matrix_a, 16, 16, 16, half, wmma::row_major> a[2];
        wmma::fragment<wmma::matrix_b, 16, 16, 16, half, wmma::row_major> b[2];
        wmma::load_matrix_sync(a[0], Xs + (warpM * 32 + 0)  * LDA + k, LDA);
        wmma::load_matrix_sync(a[1], Xs + (warpM * 32 + 16) * LDA + k, LDA);
        wmma::load_matrix_sync(b[0], Ws + k * LDA + warpN * 32 + 0,  LDA);
        wmma::load_matrix_sync(b[1], Ws + k * LDA + warpN * 32 + 16, LDA);
#pragma unroll
        for (int i = 0; i < 2; i++)
#pragma unroll
            for (int j = 0; j < 2; j++)
                wmma::mma_sync(c[i][j], a[i], b[j], c[i][j]);
    }

    __syncthreads();
    float* Cs = (float*)smem;   // [64][128]
#pragma unroll
    for (int i = 0; i < 2; i++)
#pragma unroll
        for (int j = 0; j < 2; j++)
            wmma::store_matrix_sync(Cs + (warpM * 32 + i * 16) * C + warpN * 32 + j * 16,
                                    c[i][j], C, wmma::mem_row_major);
    __syncthreads();

#pragma unroll
    for (int it = 0; it < 4; it++) {
        int idx = tid + it * 256;
        int r   = idx >> 4;
        int c8  = (idx & 15) * 8;
        int grow = row0 + r;
        if (grow < N_NODES) {
            float4 h0 = *(const float4*)(Cs + r * C + c8);
            float4 h1 = *(const float4*)(Cs + r * C + c8 + 4);
            __half2 p0 = __floats2half2_rn(h0.x, h0.y);
            __half2 p1 = __floats2half2_rn(h0.z, h0.w);
            __half2 p2 = __floats2half2_rn(h1.x, h1.y);
            __half2 p3 = __floats2half2_rn(h1.z, h1.w);
            uint4 packed;
            packed.x = *(unsigned*)&p0;
            packed.y = *(unsigned*)&p1;
            packed.z = *(unsigned*)&p2;
            packed.w = *(unsigned*)&p3;
            *(uint4*)(g_B1h + (size_t)grow * C + c8) = packed;
        }
    }

    // fused degree histogram + graph counts (layer 1 only)
    if (!TRANSFORM) {
        int gtid = blockIdx.x * 256 + tid;
        for (int e = gtid; e < N_EDGES; e += GEMM_THREADS) {
            unsigned d = (unsigned)ei[N_EDGES + e];
            if (d < N_NODES) atomicAdd(&g_deg_i[d], 1);
        }
        if (gtid < N_NODES) {
            unsigned g = (unsigned)batch[gtid];
            if (g < NG) atomicAdd(&g_cnts[g], 1.0f);
        }
    }
}

// ---------------- single-block coalesced chained scan ------------------------
__global__ __launch_bounds__(1024)
void scan_kernel() {
    __shared__ int wsum[32];
    __shared__ int carry_sh;
    int t = threadIdx.x;
    int lane = t & 31, w = t >> 5;
    if (t == 0) carry_sh = 0;
    __syncthreads();

    for (int base = 0; base < N_NODES; base += 1024) {
        int i = base + t;
        int d = (i < N_NODES) ? g_deg_i[i] : 0;

        // warp inclusive scan
        int v = d;
#pragma unroll
        for (int off = 1; off < 32; off <<= 1) {
            int u = __shfl_up_sync(FULL, v, off);
            if (lane >= off) v += u;
        }
        if (lane == 31) wsum[w] = v;
        __syncthreads();
        if (w == 0) {
            int s = wsum[lane];
#pragma unroll
            for (int off = 1; off < 32; off <<= 1) {
                int u = __shfl_up_sync(FULL, s, off);
                if (lane >= off) s += u;
            }
            wsum[lane] = s;
        }
        __syncthreads();

        int carry = carry_sh;
        int incl = carry + (w > 0 ? wsum[w - 1] : 0) + v;
        if (i < N_NODES) {
            int excl = incl - d;
            g_off[i]    = excl;
            g_cursor[i] = excl;
            g_dinv[i]   = rsqrtf((float)d + 1.0f);
        }
        __syncthreads();
        if (t == 1023) carry_sh = incl;
        __syncthreads();
    }
    if (t == 1023) g_off[N_NODES] = carry_sh;
}

// ---------------- CSR fill: permute edges by dst, packed {src, norm} ---------
__global__ void fill_kernel(const int* __restrict__ ei) {
    int e = blockIdx.x * blockDim.x + threadIdx.x;
    if (e >= N_EDGES) return;
    unsigned s = (unsigned)ei[e];
    unsigned d = (unsigned)ei[N_EDGES + e];
    if (s >= N_NODES || d >= N_NODES) return;
    int pos = atomicAdd(&g_cursor[d], 1);
    float norm = g_dinv[s] * g_dinv[d];
    g_edge[pos] = make_int2((int)s, __float_as_int(norm));
}

// ---------------- aggregation: self-loop fused, paired edge loads ------------
// Warp per dst node, lane owns 4 channels (uint2 = 4 halves).
// Edge pairs loaded as one aligned int4 (peel odd head/tail).
// AGG = B1h[node]*dinv^2 + sum_e norm_e * B1h[src_e]; v = lrelu(AGG + bias)
// POOL=false: B2h[node] = fp16(v)                        (layer 1)
// POOL=true : sums[batch[node]] += v                     (layer 2, fused pool)
template <bool POOL>
__global__ __launch_bounds__(256)
void agg_kernel(const int* __restrict__ batch, const float* __restrict__ bias)
{
    int node = (blockIdx.x * blockDim.x + threadIdx.x) >> 5;
    int lane = threadIdx.x & 31;
    if (node >= N_NODES) return;

    int beg = g_off[node];
    int end = g_off[node + 1];

    // self-loop term from own (L2-hot) row
    float d  = g_dinv[node];
    float d2 = d * d;
    uint2 su = *(const uint2*)(g_B1h + (size_t)node * C + lane * 4);
    float2 sa = __half22float2(*(__half2*)&su.x);
    float2 sb = __half22float2(*(__half2*)&su.y);

    float a0x = sa.x * d2, a0y = sa.y * d2, a0z = sb.x * d2, a0w = sb.y * d2;
    float a1x = 0.f, a1y = 0.f, a1z = 0.f, a1w = 0.f;

    int i = beg;
    if ((i & 1) && i < end) {   // peel to int4 alignment
        int2 e0 = g_edge[i];
        float n0 = __int_as_float(e0.y);
        uint2 u0 = *(const uint2*)(g_B1h + (size_t)e0.x * C + lane * 4);
        float2 f0a = __half22float2(*(__half2*)&u0.x);
        float2 f0b = __half22float2(*(__half2*)&u0.y);
        a0x += f0a.x * n0; a0y += f0a.y * n0; a0z += f0b.x * n0; a0w += f0b.y * n0;
        i++;
    }
    for (; i + 2 <= end; i += 2) {
        int4 ep = *(const int4*)(g_edge + i);   // 2 edges in one 16B uniform load
        float n0 = __int_as_float(ep.y);
        float n1 = __int_as_float(ep.w);
        uint2 u0 = *(const uint2*)(g_B1h + (size_t)ep.x * C + lane * 4);
        uint2 u1 = *(const uint2*)(g_B1h + (size_t)ep.z * C + lane * 4);
        float2 f0a = __half22float2(*(__half2*)&u0.x);
        float2 f0b = __half22float2(*(__half2*)&u0.y);
        float2 f1a = __half22float2(*(__half2*)&u1.x);
        float2 f1b = __half22float2(*(__half2*)&u1.y);
        a0x += f0a.x * n0; a0y += f0a.y * n0; a0z += f0b.x * n0; a0w += f0b.y * n0;
        a1x += f1a.x * n1; a1y += f1a.y * n1; a1z += f1b.x * n1; a1w += f1b.y * n1;
    }
    if (i < end) {
        int2 e0 = g_edge[i];
        float n0 = __int_as_float(e0.y);
        uint2 u0 = *(const uint2*)(g_B1h + (size_t)e0.x * C + lane * 4);
        float2 f0a = __half22float2(*(__half2*)&u0.x);
        float2 f0b = __half22float2(*(__half2*)&u0.y);
        a0x += f0a.x * n0; a0y += f0a.y * n0; a0z += f0b.x * n0; a0w += f0b.y * n0;
    }

    float4 b = *(const float4*)(bias + lane * 4);
    float vx = lrelu(a0x + a1x + b.x);
    float vy = lrelu(a0y + a1y + b.y);
    float vz = lrelu(a0z + a1z + b.z);
    float vw = lrelu(a0w + a1w + b.w);

    if (!POOL) {
        __half2 p0 = __floats2half2_rn(vx, vy);
        __half2 p1 = __floats2half2_rn(vz, vw);
        uint2 packed;
        packed.x = *(unsigned*)&p0;
        packed.y = *(unsigned*)&p1;
        *(uint2*)(g_B2h + (size_t)node * C + lane * 4) = packed;
    } else {
        unsigned g = (unsigned)batch[node];
        if (g >= NG) return;
        float* q = g_sums + g * C + lane * 4;
        atomicAdd(q + 0, vx);
        atomicAdd(q + 1, vy);
        atomicAdd(q + 2, vz);
        atomicAdd(q + 3, vw);
    }
}

// ---------------- MLP head ---------------------------------------------------
__global__ __launch_bounds__(128)
void head_kernel(const float* __restrict__ W3, const float* __restrict__ b3,
                 const float* __restrict__ W4, const float* __restrict__ b4,
                 const float* __restrict__ W5, const float* __restrict__ b5,
                 float* __restrict__ out)
{
    int g = blockIdx.x;
    int t = threadIdx.x;
    __shared__ float gv[128], t1[64], t2[64];

    float inv = 1.0f / fmaxf(g_cnts[g], 1.0f);
    gv[t] = g_sums[g * C + t] * inv;
    __syncthreads();

    if (t < 64) {
        float s = b3[t];
#pragma unroll 8
        for (int k = 0; k < 128; k++) s += gv[k] * W3[k * 64 + t];
        t1[t] = lrelu(s);
    }
    __syncthreads();
    if (t < 64) {
        float s = b4[t];
#pragma unroll 8
        for (int k = 0; k < 64; k++) s += t1[k] * W4[k * 64 + t];
        t2[t] = lrelu(s);
    }
    __syncthreads();
    if (t < 10) {
        float s = b5[t];
#pragma unroll 8
        for (int k = 0; k < 64; k++) s += t2[k] * W5[k * 10 + t];
        out[g * 10 + t] = s;
    }
}

// ---------------- launch ----------------------------------------------------
// Inputs resolved by ELEMENT COUNT (ordering-agnostic). edge_index/batch are
// int32 (JAX x64 disabled downcasts int64 -> int32).
extern "C" void kernel_launch(void* const* d_in, const int* in_sizes, int n_in,
                              void* d_out, int out_size)
{
    const float* x = nullptr;
    const int* ei = nullptr;
    const int* batch = nullptr;
    const float *W1 = nullptr, *b1 = nullptr, *W2 = nullptr, *b2 = nullptr;
    const float *W3 = nullptr, *b3 = nullptr, *W4 = nullptr, *b4 = nullptr;
    const float *W5 = nullptr, *b5 = nullptr;

    for (int i = 0; i < n_in; i++) {
        const void* p = d_in[i];
        switch (in_sizes[i]) {
            case 12800000: x = (const float*)p; break;
            case 3200000:  ei = (const int*)p; break;
            case 100000:   batch = (const int*)p; break;
            case 16384:    if (!W1) W1 = (const float*)p; else W2 = (const float*)p; break;
            case 8192:     W3 = (const float*)p; break;
            case 4096:     W4 = (const float*)p; break;
            case 640:      W5 = (const float*)p; break;
            case 128:      if (!b1) b1 = (const float*)p; else b2 = (const float*)p; break;
            case 64:       if (!b3) b3 = (const float*)p; else b4 = (const float*)p; break;
            case 10:       b5 = (const float*)p; break;
            default: break;
        }
    }
    float* out = (float*)d_out;
    (void)out_size;

    static bool attr_done = false;
    if (!attr_done) {
        cudaFuncSetAttribute(gemm_kernel<false>,
                             cudaFuncAttributeMaxDynamicSharedMemorySize, GEMM_SMEM);
        cudaFuncSetAttribute(gemm_kernel<true>,
                             cudaFuncAttributeMaxDynamicSharedMemorySize, GEMM_SMEM);
        attr_done = true;
    }

    // zero accumulators via async memsets (graph-capturable, no allocation)
    void *p_deg = nullptr, *p_sums = nullptr, *p_cnts = nullptr;
    cudaGetSymbolAddress(&p_deg,  g_deg_i);
    cudaGetSymbolAddress(&p_sums, g_sums);
    cudaGetSymbolAddress(&p_cnts, g_cnts);
    cudaMemsetAsync(p_deg,  0, N_NODES * sizeof(int));
    cudaMemsetAsync(p_sums, 0, NG * C * sizeof(float));
    cudaMemsetAsync(p_cnts, 0, NG * sizeof(float));

    // (1) layer-1 GEMM + fused degree histogram / graph counts
    gemm_kernel<false><<<GEMM_GRID, 256, GEMM_SMEM>>>(x, W1, ei, batch);
    // (2) single-block coalesced scan (offsets, cursors, dinv)
    scan_kernel<<<1, 1024>>>();
    // (3) CSR fill
    fill_kernel<<<(N_EDGES + 255) / 256, 256>>>(ei);
    // (4) layer-1 agg  <-- ncu capture slot
    agg_kernel<false><<<(N_NODES * 32 + 255) / 256, 256>>>(batch, b1);

    // layer 2
    gemm_kernel<true><<<GEMM_GRID, 256, GEMM_SMEM>>>(nullptr, W2, nullptr, nullptr);
    agg_kernel<true><<<(N_NODES * 32 + 255) / 256, 256>>>(batch, b2);

    // MLP head
    head_kernel<<<NG, 128>>>(W3, b3, W4, b4, W5, b5, out);
}